// round 7
// baseline (speedup 1.0000x reference)
#include <cuda_runtime.h>
#include <cuda_bf16.h>
#include <cstdint>

#define BB 4
#define NN 4096
#define DD 64
#define TM 64
#define TN 64
#define KSPLIT 2
#define KHALF (NN / KSPLIT)          // 2048 keys per CTA
#define NT2 (KHALF / TN)             // 32 tiles
#define DOT_TOL 0.1f
#define OSL (BB * NN * DD)           // partial O slice stride
#define LSL (BB * NN)                // partial l slice stride

// ---------------- device scratch (allocation-free) ----------------
__device__ __align__(16) __nv_bfloat16 g_xhi [BB * NN * DD];
__device__ __align__(16) __nv_bfloat16 g_xlo [BB * NN * DD];
__device__ __align__(16) __nv_bfloat16 g_xThi[BB * DD * NN];
__device__ __align__(16) __nv_bfloat16 g_xTlo[BB * DD * NN];
__device__ __align__(16) float g_rn [BB * NN];
__device__ __align__(16) float g_rnb[BB * NN];
__device__ __align__(16) float g_po[KSPLIT * OSL];   // unnormalized O partials
__device__ __align__(16) float g_pl[KSPLIT * LSL];   // row-sum partials

// ---------------- helpers ----------------
__device__ __forceinline__ uint32_t smem_u32(const void* p) {
    uint32_t a;
    asm("{ .reg .u64 t; cvta.to.shared.u64 t, %1; cvt.u32.u64 %0, t; }" : "=r"(a) : "l"(p));
    return a;
}
#define SW(o) ((o) ^ (((o) >> 3) & 0x70))
#define CPA(dst, src) asm volatile("cp.async.cg.shared.global [%0], [%1], 16;" :: "r"(dst), "l"(src))
#define CPC()   asm volatile("cp.async.commit_group;" ::: "memory")
#define CPW0()  asm volatile("cp.async.wait_group 0;" ::: "memory")

__device__ __forceinline__ void ldsm4(uint32_t& r0, uint32_t& r1, uint32_t& r2, uint32_t& r3, uint32_t a) {
    asm volatile("ldmatrix.sync.aligned.m8n8.x4.shared.b16 {%0,%1,%2,%3}, [%4];"
                 : "=r"(r0), "=r"(r1), "=r"(r2), "=r"(r3) : "r"(a));
}
__device__ __forceinline__ void mma16816(float* d, const uint32_t* a, const uint32_t* b) {
    asm volatile("mma.sync.aligned.m16n8k16.row.col.f32.bf16.bf16.f32 "
                 "{%0,%1,%2,%3}, {%4,%5,%6,%7}, {%8,%9}, {%0,%1,%2,%3};"
                 : "+f"(d[0]), "+f"(d[1]), "+f"(d[2]), "+f"(d[3])
                 : "r"(a[0]), "r"(a[1]), "r"(a[2]), "r"(a[3]), "r"(b[0]), "r"(b[1]));
}
__device__ __forceinline__ uint32_t pack2(__nv_bfloat16 a, __nv_bfloat16 b) {
    return (uint32_t)__bfloat16_as_ushort(a) | ((uint32_t)__bfloat16_as_ushort(b) << 16);
}

// cold-path exact fp32 dot (sign rescue)
__device__ __noinline__ float dot64(const float* __restrict__ a, const float* __restrict__ b) {
    float acc = 0.f;
    #pragma unroll
    for (int i = 0; i < 16; ++i) {
        float4 va = __ldg((const float4*)a + i);
        float4 vb = __ldg((const float4*)b + i);
        acc = fmaf(va.x, vb.x, acc); acc = fmaf(va.y, vb.y, acc);
        acc = fmaf(va.z, vb.z, acc); acc = fmaf(va.w, vb.w, acc);
    }
    return acc;
}

// ---------------- prep ----------------
__global__ __launch_bounds__(256) void prep_kernel(const float* __restrict__ x,
                                                   const float* __restrict__ betap) {
    __shared__ float s[64][68];
    const int row0 = blockIdx.x * 64;
    const int tid = threadIdx.x;

    for (int i = tid; i < 64 * 16; i += 256) {
        int r = i >> 4, c4 = (i & 15) << 2;
        float4 v = *(const float4*)&x[(size_t)(row0 + r) * DD + c4];
        s[r][c4] = v.x; s[r][c4 + 1] = v.y; s[r][c4 + 2] = v.z; s[r][c4 + 3] = v.w;
    }
    __syncthreads();

    const float beta = __ldg(betap);
    if (tid < 64) {
        float acc = 0.f;
        #pragma unroll
        for (int d = 0; d < 64; ++d) acc = fmaf(s[tid][d], s[tid][d], acc);
        float rn = 1.0f / sqrtf(acc);
        g_rn[row0 + tid] = rn;
        g_rnb[row0 + tid] = beta * rn;
    }

    {   // row-major hi/lo
        int base = tid * 16;
        int r = base >> 6, c = base & 63;
        uint32_t hb[8], lb[8];
        #pragma unroll
        for (int j = 0; j < 8; ++j) {
            float a = s[r][c + 2 * j], b = s[r][c + 2 * j + 1];
            __nv_bfloat16 ah = __float2bfloat16(a), bh = __float2bfloat16(b);
            __nv_bfloat16 al = __float2bfloat16(a - __bfloat162float(ah));
            __nv_bfloat16 bl = __float2bfloat16(b - __bfloat162float(bh));
            hb[j] = pack2(ah, bh); lb[j] = pack2(al, bl);
        }
        uint4* dh = (uint4*)(g_xhi + (size_t)row0 * DD + base);
        uint4* dl = (uint4*)(g_xlo + (size_t)row0 * DD + base);
        dh[0] = make_uint4(hb[0], hb[1], hb[2], hb[3]); dh[1] = make_uint4(hb[4], hb[5], hb[6], hb[7]);
        dl[0] = make_uint4(lb[0], lb[1], lb[2], lb[3]); dl[1] = make_uint4(lb[4], lb[5], lb[6], lb[7]);
    }
    {   // transposed hi/lo
        int d = tid >> 2, j0 = (tid & 3) * 16;
        int b = row0 / NN, n0 = row0 % NN;
        uint32_t hb[8], lb[8];
        #pragma unroll
        for (int j = 0; j < 8; ++j) {
            float a = s[j0 + 2 * j][d], bb = s[j0 + 2 * j + 1][d];
            __nv_bfloat16 ah = __float2bfloat16(a), bh = __float2bfloat16(bb);
            __nv_bfloat16 al = __float2bfloat16(a - __bfloat162float(ah));
            __nv_bfloat16 bl = __float2bfloat16(bb - __bfloat162float(bh));
            hb[j] = pack2(ah, bh); lb[j] = pack2(al, bl);
        }
        size_t off = (size_t)(b * DD + d) * NN + n0 + j0;
        uint4* dh = (uint4*)(g_xThi + off);
        uint4* dl = (uint4*)(g_xTlo + off);
        dh[0] = make_uint4(hb[0], hb[1], hb[2], hb[3]); dh[1] = make_uint4(hb[4], hb[5], hb[6], hb[7]);
        dl[0] = make_uint4(lb[0], lb[1], lb[2], lb[3]); dl[1] = make_uint4(lb[4], lb[5], lb[6], lb[7]);
    }
}

// ---------------- smem layout ----------------
// Q hi only: 8K; stages: 2 x (Khi 8K | Klo 8K | Vhi 8K | Vlo 8K) = 64K
#define OFF_Q   0
#define OFF_ST  8192
#define SMEM_TOTAL (8192 + 2 * 32768)

__device__ __forceinline__ void load_stage(uint32_t stbase, int tid, int b, int k0) {
    const __nv_bfloat16* kh = g_xhi + ((size_t)b * NN + k0) * DD;
    const __nv_bfloat16* kl = g_xlo + ((size_t)b * NN + k0) * DD;
    const __nv_bfloat16* vh = g_xThi + (size_t)b * DD * NN + k0;
    const __nv_bfloat16* vl = g_xTlo + (size_t)b * DD * NN + k0;
    #pragma unroll
    for (int it = 0; it < 16; ++it) {
        int m = tid + it * 128;
        int buf = m >> 9, idx = m & 511, r = idx >> 3, c = idx & 7;
        uint32_t dst = stbase + buf * 8192 + SW(r * 128 + c * 16);
        const __nv_bfloat16* src;
        if (buf == 0)      src = kh + r * 64 + c * 8;
        else if (buf == 1) src = kl + r * 64 + c * 8;
        else if (buf == 2) src = vh + (size_t)r * NN + c * 8;
        else               src = vl + (size_t)r * NN + c * 8;
        CPA(dst, src);
    }
}

// ---------------- main kernel: split-K, 128 threads, 3 CTAs/SM ----------------
__global__ __launch_bounds__(128, 3)
void attn_mma(const float* __restrict__ x,
              const float* __restrict__ adj,
              const float* __restrict__ betap) {
    extern __shared__ char smem[];
    const uint32_t sb = smem_u32(smem);
    const int tid = threadIdx.x;
    const int wid = tid >> 5, lane = tid & 31;
    const int g = lane >> 2, t = lane & 3;
    const int b = blockIdx.y, q0 = blockIdx.x * TM;
    const int z = blockIdx.z;                 // key half
    const int kbase = z * KHALF;
    const size_t bNN = (size_t)b * NN;

    const int lm = lane >> 3, li = lane & 7;
    const uint32_t b_row = ((lm >> 1) << 3) + li;
    const uint32_t b_kb  = (uint32_t)(lm & 1) << 4;
    const uint32_t a_row = ((uint32_t)(lm & 1) << 3) + li + wid * 16;
    const uint32_t a_kb  = (uint32_t)(lm >> 1) << 4;

    // prologue: Q hi + tile0
    {
        const __nv_bfloat16* qh = g_xhi + (bNN + q0) * DD;
        #pragma unroll
        for (int it = 0; it < 4; ++it) {
            int m = tid + it * 128;
            int r = m >> 3, c = m & 7;
            CPA(sb + OFF_Q + SW(r * 128 + c * 16), qh + r * 64 + c * 8);
        }
        load_stage(sb + OFF_ST, tid, b, kbase);
        CPC();
    }

    const float beta = __ldg(betap);
    const float C = beta + 10.0f;
    const float rq0 = g_rn[bNN + q0 + wid * 16 + g];
    const float rq1 = g_rn[bNN + q0 + wid * 16 + g + 8];
    const float* adjrow = adj + (bNN + q0 + wid * 16 + g) * (size_t)NN + 2 * t;
    const float* xb  = x + bNN * DD;
    const float* xq0 = xb + (size_t)(q0 + wid * 16 + g) * DD;
    const float* xq1 = xq0 + 8 * DD;

    uint32_t qhiF[4][4];
    float o[8][4];
    #pragma unroll
    for (int j = 0; j < 8; ++j)
        { o[j][0] = 0.f; o[j][1] = 0.f; o[j][2] = 0.f; o[j][3] = 0.f; }
    float lsum0 = 0.f, lsum1 = 0.f;

    for (int tt = 0; tt < NT2; ++tt) {
        const int k0 = kbase + tt * TN;
        CPW0();
        __syncthreads();
        if (tt + 1 < NT2) {
            load_stage(sb + OFF_ST + ((tt + 1) & 1) * 32768, tid, b, k0 + TN);
            CPC();
        }
        if (tt == 0) {
            #pragma unroll
            for (int ks = 0; ks < 4; ++ks) {
                uint32_t ad = sb + OFF_Q + SW(a_row * 128 + ks * 32 + a_kb);
                ldsm4(qhiF[ks][0], qhiF[ks][1], qhiF[ks][2], qhiF[ks][3], ad);
            }
        }
        const uint32_t stb = sb + OFF_ST + (tt & 1) * 32768;

        // adj prefetch (overlaps with the S mma)
        float2 av0[8], av1[8];
        {
            const float* ar0 = adjrow + k0;
            const float* ar1 = ar0 + (size_t)8 * NN;
            #pragma unroll
            for (int j = 0; j < 8; ++j) {
                av0[j] = __ldg((const float2*)(ar0 + 8 * j));
                av1[j] = __ldg((const float2*)(ar1 + 8 * j));
            }
        }

        // ---- S = Qhi*(Khi + Klo) : 2-term split (rescue covers sign band) ----
        float s[8][4];
        #pragma unroll
        for (int j = 0; j < 8; ++j)
            { s[j][0] = 0.f; s[j][1] = 0.f; s[j][2] = 0.f; s[j][3] = 0.f; }

        #pragma unroll
        for (int ks = 0; ks < 4; ++ks) {
            uint32_t bf[8][2];
            #pragma unroll
            for (int nb = 0; nb < 4; ++nb) {
                uint32_t ad = stb + SW((nb * 16 + b_row) * 128 + ks * 32 + b_kb);
                ldsm4(bf[2 * nb][0], bf[2 * nb][1], bf[2 * nb + 1][0], bf[2 * nb + 1][1], ad);
            }
            #pragma unroll
            for (int j = 0; j < 8; ++j) { mma16816(s[j], qhiF[ks], bf[j]); }
            #pragma unroll
            for (int nb = 0; nb < 4; ++nb) {
                uint32_t ad = stb + 8192 + SW((nb * 16 + b_row) * 128 + ks * 32 + b_kb);
                ldsm4(bf[2 * nb][0], bf[2 * nb][1], bf[2 * nb + 1][0], bf[2 * nb + 1][1], ad);
            }
            #pragma unroll
            for (int j = 0; j < 8; ++j) { mma16816(s[j], qhiF[ks], bf[j]); }
        }

        // ---- logits -> exp -> pack P ----
        uint32_t ahi[4][4], alo[4][4];
        {
            const float* rnbp = g_rnb + bNN + k0 + 2 * t;
            #pragma unroll
            for (int j = 0; j < 8; ++j) {
                {   // cold fp32 sign rescue
                    bool n0 = (av0[j].x > 0.5f) && (fabsf(s[j][0]) < DOT_TOL);
                    bool n1 = (av0[j].y > 0.5f) && (fabsf(s[j][1]) < DOT_TOL);
                    bool n2 = (av1[j].x > 0.5f) && (fabsf(s[j][2]) < DOT_TOL);
                    bool n3 = (av1[j].y > 0.5f) && (fabsf(s[j][3]) < DOT_TOL);
                    if (n0 | n1 | n2 | n3) {
                        const int kk = k0 + 8 * j + 2 * t;
                        if (n0) s[j][0] = dot64(xq0, xb + (size_t)kk * DD);
                        if (n1) s[j][1] = dot64(xq0, xb + (size_t)(kk + 1) * DD);
                        if (n2) s[j][2] = dot64(xq1, xb + (size_t)kk * DD);
                        if (n3) s[j][3] = dot64(xq1, xb + (size_t)(kk + 1) * DD);
                    }
                }
                float2 rk = __ldg((const float2*)(rnbp + 8 * j));
                float r00 = rq0 * rk.x, r01 = rq0 * rk.y;
                float r10 = rq1 * rk.x, r11 = rq1 * rk.y;
                float lg0 = (s[j][0] < 0.f) ? -1e30f : fmaf(10.f, av0[j].x, fmaf(s[j][0], r00, -C));
                float lg1 = (s[j][1] < 0.f) ? -1e30f : fmaf(10.f, av0[j].y, fmaf(s[j][1], r01, -C));
                float lg2 = (s[j][2] < 0.f) ? -1e30f : fmaf(10.f, av1[j].x, fmaf(s[j][2], r10, -C));
                float lg3 = (s[j][3] < 0.f) ? -1e30f : fmaf(10.f, av1[j].y, fmaf(s[j][3], r11, -C));
                float p0 = __expf(lg0), p1 = __expf(lg1), p2 = __expf(lg2), p3 = __expf(lg3);
                lsum0 += p0 + p1; lsum1 += p2 + p3;
                uint32_t h01, h23;
                asm("cvt.rn.bf16x2.f32 %0, %1, %2;" : "=r"(h01) : "f"(p1), "f"(p0));
                asm("cvt.rn.bf16x2.f32 %0, %1, %2;" : "=r"(h23) : "f"(p3), "f"(p2));
                float hf0 = __uint_as_float(h01 << 16), hf1 = __uint_as_float(h01 & 0xFFFF0000u);
                float hf2 = __uint_as_float(h23 << 16), hf3 = __uint_as_float(h23 & 0xFFFF0000u);
                uint32_t l01, l23;
                asm("cvt.rn.bf16x2.f32 %0, %1, %2;" : "=r"(l01) : "f"(p1 - hf1), "f"(p0 - hf0));
                asm("cvt.rn.bf16x2.f32 %0, %1, %2;" : "=r"(l23) : "f"(p3 - hf3), "f"(p2 - hf2));
                int cc = j >> 1, h = (j & 1) << 1;
                ahi[cc][h] = h01; ahi[cc][h + 1] = h23;
                alo[cc][h] = l01; alo[cc][h + 1] = l23;
            }
        }

        // ---- O += P V : 3-term split ----
        #pragma unroll
        for (int c = 0; c < 4; ++c) {
            uint32_t bf[8][2];
            #pragma unroll
            for (int nb = 0; nb < 4; ++nb) {
                uint32_t ad = stb + 16384 + SW((nb * 16 + b_row) * 128 + c * 32 + b_kb);
                ldsm4(bf[2 * nb][0], bf[2 * nb][1], bf[2 * nb + 1][0], bf[2 * nb + 1][1], ad);
            }
            #pragma unroll
            for (int j = 0; j < 8; ++j) { mma16816(o[j], ahi[c], bf[j]); mma16816(o[j], alo[c], bf[j]); }
            #pragma unroll
            for (int nb = 0; nb < 4; ++nb) {
                uint32_t ad = stb + 24576 + SW((nb * 16 + b_row) * 128 + c * 32 + b_kb);
                ldsm4(bf[2 * nb][0], bf[2 * nb][1], bf[2 * nb + 1][0], bf[2 * nb + 1][1], ad);
            }
            #pragma unroll
            for (int j = 0; j < 8; ++j) { mma16816(o[j], ahi[c], bf[j]); }
        }
    }

    // ---- epilogue: write unnormalized partials ----
    lsum0 += __shfl_xor_sync(0xffffffffu, lsum0, 1);
    lsum0 += __shfl_xor_sync(0xffffffffu, lsum0, 2);
    lsum1 += __shfl_xor_sync(0xffffffffu, lsum1, 1);
    lsum1 += __shfl_xor_sync(0xffffffffu, lsum1, 2);

    const int row0 = (int)(bNN) + q0 + wid * 16 + g;
    if (t == 0) {
        g_pl[z * LSL + row0] = lsum0;
        g_pl[z * LSL + row0 + 8] = lsum1;
    }
    float* po0 = g_po + z * OSL + (size_t)row0 * DD + 2 * t;
    float* po1 = po0 + 8 * DD;
    #pragma unroll
    for (int j = 0; j < 8; ++j) {
        *(float2*)(po0 + 8 * j) = make_float2(o[j][0], o[j][1]);
        *(float2*)(po1 + 8 * j) = make_float2(o[j][2], o[j][3]);
    }
}

// ---------------- reduce: out = (O0+O1)/(l0+l1) ----------------
__global__ __launch_bounds__(256) void reduce_kernel(float* __restrict__ out) {
    int idx = blockIdx.x * 256 + threadIdx.x;   // 0 .. OSL/4-1
    int base = idx * 4;
    int row = base >> 6;
    float inv = 1.0f / (g_pl[row] + g_pl[LSL + row]);
    float4 a = *(const float4*)(g_po + base);
    float4 b = *(const float4*)(g_po + OSL + base);
    *(float4*)(out + base) = make_float4((a.x + b.x) * inv, (a.y + b.y) * inv,
                                         (a.z + b.z) * inv, (a.w + b.w) * inv);
}

// ---------------------------------------------------------------------------
extern "C" void kernel_launch(void* const* d_in, const int* in_sizes, int n_in,
                              void* d_out, int out_size) {
    (void)in_sizes; (void)n_in; (void)out_size;
    const float* x    = (const float*)d_in[0];
    const float* adj  = (const float*)d_in[1];
    const float* beta = (const float*)d_in[2];
    float* out = (float*)d_out;

    prep_kernel<<<BB * NN / 64, 256>>>(x, beta);

    cudaFuncSetAttribute(attn_mma, cudaFuncAttributeMaxDynamicSharedMemorySize, SMEM_TOTAL);
    dim3 grid(NN / TM, BB, KSPLIT);
    attn_mma<<<grid, 128, SMEM_TOTAL>>>(x, adj, beta);

    reduce_kernel<<<OSL / 4 / 256, 256>>>(out);
}

// round 8
// speedup vs baseline: 1.1644x; 1.1644x over previous
#include <cuda_runtime.h>
#include <cuda_bf16.h>
#include <cstdint>

#define BB 4
#define NN 4096
#define DD 64
#define TM 64
#define TN 64
#define NTILES (NN / TN)
#define DOT_TOL 0.1f

// ---------------- device scratch (allocation-free) ----------------
__device__ __align__(16) __nv_bfloat16 g_xhi [BB * NN * DD];
__device__ __align__(16) __nv_bfloat16 g_xlo [BB * NN * DD];
__device__ __align__(16) __nv_bfloat16 g_xThi[BB * DD * NN];
__device__ __align__(16) __nv_bfloat16 g_xTlo[BB * DD * NN];
__device__ __align__(16) float g_rn [BB * NN];
__device__ __align__(16) float g_rnb[BB * NN];

// ---------------- helpers ----------------
__device__ __forceinline__ uint32_t smem_u32(const void* p) {
    uint32_t a;
    asm("{ .reg .u64 t; cvta.to.shared.u64 t, %1; cvt.u32.u64 %0, t; }" : "=r"(a) : "l"(p));
    return a;
}
#define SW(o) ((o) ^ (((o) >> 3) & 0x70))
#define CPA(dst, src) asm volatile("cp.async.cg.shared.global [%0], [%1], 16;" :: "r"(dst), "l"(src))
#define CPC()   asm volatile("cp.async.commit_group;" ::: "memory")
#define CPW0()  asm volatile("cp.async.wait_group 0;" ::: "memory")

__device__ __forceinline__ void ldsm4(uint32_t& r0, uint32_t& r1, uint32_t& r2, uint32_t& r3, uint32_t a) {
    asm volatile("ldmatrix.sync.aligned.m8n8.x4.shared.b16 {%0,%1,%2,%3}, [%4];"
                 : "=r"(r0), "=r"(r1), "=r"(r2), "=r"(r3) : "r"(a));
}
__device__ __forceinline__ void mma16816(float* d, const uint32_t* a, const uint32_t* b) {
    asm volatile("mma.sync.aligned.m16n8k16.row.col.f32.bf16.bf16.f32 "
                 "{%0,%1,%2,%3}, {%4,%5,%6,%7}, {%8,%9}, {%0,%1,%2,%3};"
                 : "+f"(d[0]), "+f"(d[1]), "+f"(d[2]), "+f"(d[3])
                 : "r"(a[0]), "r"(a[1]), "r"(a[2]), "r"(a[3]), "r"(b[0]), "r"(b[1]));
}
__device__ __forceinline__ uint32_t pack2(__nv_bfloat16 a, __nv_bfloat16 b) {
    return (uint32_t)__bfloat16_as_ushort(a) | ((uint32_t)__bfloat16_as_ushort(b) << 16);
}

// cold-path exact fp32 dot (sign rescue)
__device__ __noinline__ float dot64(const float* __restrict__ a, const float* __restrict__ b) {
    float acc = 0.f;
    #pragma unroll
    for (int i = 0; i < 16; ++i) {
        float4 va = __ldg((const float4*)a + i);
        float4 vb = __ldg((const float4*)b + i);
        acc = fmaf(va.x, vb.x, acc); acc = fmaf(va.y, vb.y, acc);
        acc = fmaf(va.z, vb.z, acc); acc = fmaf(va.w, vb.w, acc);
    }
    return acc;
}

// ---------------- prep ----------------
__global__ __launch_bounds__(256) void prep_kernel(const float* __restrict__ x,
                                                   const float* __restrict__ betap) {
    __shared__ float s[64][68];
    const int row0 = blockIdx.x * 64;
    const int tid = threadIdx.x;

    for (int i = tid; i < 64 * 16; i += 256) {
        int r = i >> 4, c4 = (i & 15) << 2;
        float4 v = *(const float4*)&x[(size_t)(row0 + r) * DD + c4];
        s[r][c4] = v.x; s[r][c4 + 1] = v.y; s[r][c4 + 2] = v.z; s[r][c4 + 3] = v.w;
    }
    __syncthreads();

    const float beta = __ldg(betap);
    if (tid < 64) {
        float acc = 0.f;
        #pragma unroll
        for (int d = 0; d < 64; ++d) acc = fmaf(s[tid][d], s[tid][d], acc);
        float rn = 1.0f / sqrtf(acc);
        g_rn[row0 + tid] = rn;
        g_rnb[row0 + tid] = beta * rn;
    }

    {   // row-major hi/lo
        int base = tid * 16;
        int r = base >> 6, c = base & 63;
        uint32_t hb[8], lb[8];
        #pragma unroll
        for (int j = 0; j < 8; ++j) {
            float a = s[r][c + 2 * j], b = s[r][c + 2 * j + 1];
            __nv_bfloat16 ah = __float2bfloat16(a), bh = __float2bfloat16(b);
            __nv_bfloat16 al = __float2bfloat16(a - __bfloat162float(ah));
            __nv_bfloat16 bl = __float2bfloat16(b - __bfloat162float(bh));
            hb[j] = pack2(ah, bh); lb[j] = pack2(al, bl);
        }
        uint4* dh = (uint4*)(g_xhi + (size_t)row0 * DD + base);
        uint4* dl = (uint4*)(g_xlo + (size_t)row0 * DD + base);
        dh[0] = make_uint4(hb[0], hb[1], hb[2], hb[3]); dh[1] = make_uint4(hb[4], hb[5], hb[6], hb[7]);
        dl[0] = make_uint4(lb[0], lb[1], lb[2], lb[3]); dl[1] = make_uint4(lb[4], lb[5], lb[6], lb[7]);
    }
    {   // transposed hi/lo
        int d = tid >> 2, j0 = (tid & 3) * 16;
        int b = row0 / NN, n0 = row0 % NN;
        uint32_t hb[8], lb[8];
        #pragma unroll
        for (int j = 0; j < 8; ++j) {
            float a = s[j0 + 2 * j][d], bb = s[j0 + 2 * j + 1][d];
            __nv_bfloat16 ah = __float2bfloat16(a), bh = __float2bfloat16(bb);
            __nv_bfloat16 al = __float2bfloat16(a - __bfloat162float(ah));
            __nv_bfloat16 bl = __float2bfloat16(bb - __bfloat162float(bh));
            hb[j] = pack2(ah, bh); lb[j] = pack2(al, bl);
        }
        size_t off = (size_t)(b * DD + d) * NN + n0 + j0;
        uint4* dh = (uint4*)(g_xThi + off);
        uint4* dl = (uint4*)(g_xTlo + off);
        dh[0] = make_uint4(hb[0], hb[1], hb[2], hb[3]); dh[1] = make_uint4(hb[4], hb[5], hb[6], hb[7]);
        dl[0] = make_uint4(lb[0], lb[1], lb[2], lb[3]); dl[1] = make_uint4(lb[4], lb[5], lb[6], lb[7]);
    }
}

// ---------------- smem layout ----------------
// Q hi: 8K; stages: 2 x (Khi 8K | Klo 8K | Vhi 8K | Vlo 8K) = 64K
#define OFF_Q   0
#define OFF_ST  8192
#define SMEM_TOTAL (8192 + 2 * 32768)

__device__ __forceinline__ void load_stage(uint32_t stbase, int tid, int b, int k0) {
    const __nv_bfloat16* kh = g_xhi + ((size_t)b * NN + k0) * DD;
    const __nv_bfloat16* kl = g_xlo + ((size_t)b * NN + k0) * DD;
    const __nv_bfloat16* vh = g_xThi + (size_t)b * DD * NN + k0;
    const __nv_bfloat16* vl = g_xTlo + (size_t)b * DD * NN + k0;
    #pragma unroll
    for (int it = 0; it < 8; ++it) {
        int m = tid + it * 256;
        int buf = m >> 9, idx = m & 511, r = idx >> 3, c = idx & 7;
        uint32_t dst = stbase + buf * 8192 + SW(r * 128 + c * 16);
        const __nv_bfloat16* src;
        if (buf == 0)      src = kh + r * 64 + c * 8;
        else if (buf == 1) src = kl + r * 64 + c * 8;
        else if (buf == 2) src = vh + (size_t)r * NN + c * 8;
        else               src = vl + (size_t)r * NN + c * 8;
        CPA(dst, src);
    }
}

// ---------------- main kernel: 256 threads, key-split warps, 2 CTAs/SM ----------------
__global__ __launch_bounds__(256, 2)
void attn_mma(const float* __restrict__ x,
              const float* __restrict__ adj,
              const float* __restrict__ betap,
              float* __restrict__ out) {
    extern __shared__ char smem[];
    const uint32_t sb = smem_u32(smem);
    const int tid = threadIdx.x;
    const int wid = tid >> 5, lane = tid & 31;
    const int qr = wid >> 1;          // query row group: rows 16*qr .. 16*qr+15
    const int h  = wid & 1;           // key half within tile: keys 32h .. 32h+31
    const int g = lane >> 2, t = lane & 3;
    const int b = blockIdx.y, q0 = blockIdx.x * TM;
    const size_t bNN = (size_t)b * NN;

    const int lm = lane >> 3, li = lane & 7;
    const uint32_t b_row = ((lm >> 1) << 3) + li;
    const uint32_t b_kb  = (uint32_t)(lm & 1) << 4;
    const uint32_t a_row = ((uint32_t)(lm & 1) << 3) + li + qr * 16;
    const uint32_t a_kb  = (uint32_t)(lm >> 1) << 4;

    // prologue: Q hi + tile0
    {
        const __nv_bfloat16* qh = g_xhi + (bNN + q0) * DD;
        #pragma unroll
        for (int it = 0; it < 2; ++it) {
            int m = tid + it * 256;
            int r = m >> 3, c = m & 7;
            CPA(sb + OFF_Q + SW(r * 128 + c * 16), qh + r * 64 + c * 8);
        }
        load_stage(sb + OFF_ST, tid, b, 0);
        CPC();
    }

    const float beta = __ldg(betap);
    const float C = beta + 10.0f;
    const int qrow = q0 + qr * 16 + g;
    const float rq0 = g_rn[bNN + qrow];
    const float rq1 = g_rn[bNN + qrow + 8];
    const float* adjrow = adj + (bNN + qrow) * (size_t)NN + 32 * h + 2 * t;
    const float* xb  = x + bNN * DD;
    const float* xq0 = xb + (size_t)qrow * DD;
    const float* xq1 = xq0 + 8 * DD;

    uint32_t qhiF[4][4];
    float o[8][4];
    #pragma unroll
    for (int j = 0; j < 8; ++j)
        { o[j][0] = 0.f; o[j][1] = 0.f; o[j][2] = 0.f; o[j][3] = 0.f; }
    float lsum0 = 0.f, lsum1 = 0.f;

    for (int tt = 0; tt < NTILES; ++tt) {
        const int k0 = tt * TN;
        CPW0();
        __syncthreads();
        if (tt + 1 < NTILES) {
            load_stage(sb + OFF_ST + ((tt + 1) & 1) * 32768, tid, b, k0 + TN);
            CPC();
        }
        if (tt == 0) {
            #pragma unroll
            for (int ks = 0; ks < 4; ++ks) {
                uint32_t ad = sb + OFF_Q + SW(a_row * 128 + ks * 32 + a_kb);
                ldsm4(qhiF[ks][0], qhiF[ks][1], qhiF[ks][2], qhiF[ks][3], ad);
            }
        }
        const uint32_t stb = sb + OFF_ST + (tt & 1) * 32768;

        // adj prefetch for this warp's key half (overlaps the S mma)
        float2 av0[4], av1[4];
        {
            const float* ar0 = adjrow + k0;
            const float* ar1 = ar0 + (size_t)8 * NN;
            #pragma unroll
            for (int j = 0; j < 4; ++j) {
                av0[j] = __ldg((const float2*)(ar0 + 8 * j));
                av1[j] = __ldg((const float2*)(ar1 + 8 * j));
            }
        }

        // ---- S = Qhi*(Khi + Klo), 16x32 tile per warp ----
        float s[4][4];
        #pragma unroll
        for (int j = 0; j < 4; ++j)
            { s[j][0] = 0.f; s[j][1] = 0.f; s[j][2] = 0.f; s[j][3] = 0.f; }

        #pragma unroll
        for (int ks = 0; ks < 4; ++ks) {
            uint32_t bf[4][2];
            #pragma unroll
            for (int nb = 0; nb < 2; ++nb) {
                uint32_t ad = stb + SW((32 * h + nb * 16 + b_row) * 128 + ks * 32 + b_kb);
                ldsm4(bf[2 * nb][0], bf[2 * nb][1], bf[2 * nb + 1][0], bf[2 * nb + 1][1], ad);
            }
            #pragma unroll
            for (int j = 0; j < 4; ++j) mma16816(s[j], qhiF[ks], bf[j]);
            #pragma unroll
            for (int nb = 0; nb < 2; ++nb) {
                uint32_t ad = stb + 8192 + SW((32 * h + nb * 16 + b_row) * 128 + ks * 32 + b_kb);
                ldsm4(bf[2 * nb][0], bf[2 * nb][1], bf[2 * nb + 1][0], bf[2 * nb + 1][1], ad);
            }
            #pragma unroll
            for (int j = 0; j < 4; ++j) mma16816(s[j], qhiF[ks], bf[j]);
        }

        // ---- logits -> exp -> pack P ----
        uint32_t ahi[2][4], alo[2][4];
        {
            const float* rnbp = g_rnb + bNN + k0 + 32 * h + 2 * t;
            #pragma unroll
            for (int j = 0; j < 4; ++j) {
                {   // cold fp32 sign rescue
                    bool n0 = (av0[j].x > 0.5f) && (fabsf(s[j][0]) < DOT_TOL);
                    bool n1 = (av0[j].y > 0.5f) && (fabsf(s[j][1]) < DOT_TOL);
                    bool n2 = (av1[j].x > 0.5f) && (fabsf(s[j][2]) < DOT_TOL);
                    bool n3 = (av1[j].y > 0.5f) && (fabsf(s[j][3]) < DOT_TOL);
                    if (n0 | n1 | n2 | n3) {
                        const int kk = k0 + 32 * h + 8 * j + 2 * t;
                        if (n0) s[j][0] = dot64(xq0, xb + (size_t)kk * DD);
                        if (n1) s[j][1] = dot64(xq0, xb + (size_t)(kk + 1) * DD);
                        if (n2) s[j][2] = dot64(xq1, xb + (size_t)kk * DD);
                        if (n3) s[j][3] = dot64(xq1, xb + (size_t)(kk + 1) * DD);
                    }
                }
                float2 rk = __ldg((const float2*)(rnbp + 8 * j));
                float lg0 = (s[j][0] < 0.f) ? -1e30f : fmaf(10.f, av0[j].x, fmaf(s[j][0], rq0 * rk.x, -C));
                float lg1 = (s[j][1] < 0.f) ? -1e30f : fmaf(10.f, av0[j].y, fmaf(s[j][1], rq0 * rk.y, -C));
                float lg2 = (s[j][2] < 0.f) ? -1e30f : fmaf(10.f, av1[j].x, fmaf(s[j][2], rq1 * rk.x, -C));
                float lg3 = (s[j][3] < 0.f) ? -1e30f : fmaf(10.f, av1[j].y, fmaf(s[j][3], rq1 * rk.y, -C));
                float p0 = __expf(lg0), p1 = __expf(lg1), p2 = __expf(lg2), p3 = __expf(lg3);
                lsum0 += p0 + p1; lsum1 += p2 + p3;
                uint32_t h01, h23;
                asm("cvt.rn.bf16x2.f32 %0, %1, %2;" : "=r"(h01) : "f"(p1), "f"(p0));
                asm("cvt.rn.bf16x2.f32 %0, %1, %2;" : "=r"(h23) : "f"(p3), "f"(p2));
                float hf0 = __uint_as_float(h01 << 16), hf1 = __uint_as_float(h01 & 0xFFFF0000u);
                float hf2 = __uint_as_float(h23 << 16), hf3 = __uint_as_float(h23 & 0xFFFF0000u);
                uint32_t l01, l23;
                asm("cvt.rn.bf16x2.f32 %0, %1, %2;" : "=r"(l01) : "f"(p1 - hf1), "f"(p0 - hf0));
                asm("cvt.rn.bf16x2.f32 %0, %1, %2;" : "=r"(l23) : "f"(p3 - hf3), "f"(p2 - hf2));
                int cc = j >> 1, hp = (j & 1) << 1;
                ahi[cc][hp] = h01; ahi[cc][hp + 1] = h23;
                alo[cc][hp] = l01; alo[cc][hp + 1] = l23;
            }
        }

        // ---- O += P V over this warp's 32 keys, all 64 dims ----
        #pragma unroll
        for (int cl = 0; cl < 2; ++cl) {
            const int c = 2 * h + cl;
            uint32_t bf[8][2];
            #pragma unroll
            for (int nb = 0; nb < 4; ++nb) {
                uint32_t ad = stb + 16384 + SW((nb * 16 + b_row) * 128 + c * 32 + b_kb);
                ldsm4(bf[2 * nb][0], bf[2 * nb][1], bf[2 * nb + 1][0], bf[2 * nb + 1][1], ad);
            }
            #pragma unroll
            for (int j = 0; j < 8; ++j) { mma16816(o[j], ahi[cl], bf[j]); mma16816(o[j], alo[cl], bf[j]); }
            #pragma unroll
            for (int nb = 0; nb < 4; ++nb) {
                uint32_t ad = stb + 24576 + SW((nb * 16 + b_row) * 128 + c * 32 + b_kb);
                ldsm4(bf[2 * nb][0], bf[2 * nb][1], bf[2 * nb + 1][0], bf[2 * nb + 1][1], ad);
            }
            #pragma unroll
            for (int j = 0; j < 8; ++j) mma16816(o[j], ahi[cl], bf[j]);
        }
    }

    // ---- epilogue: combine key halves via smem, normalize, store ----
    lsum0 += __shfl_xor_sync(0xffffffffu, lsum0, 1);
    lsum0 += __shfl_xor_sync(0xffffffffu, lsum0, 2);
    lsum1 += __shfl_xor_sync(0xffffffffu, lsum1, 1);
    lsum1 += __shfl_xor_sync(0xffffffffu, lsum1, 2);

    __syncthreads();   // all stage-buffer reads done; safe to reuse as O buffer
    float* obuf = (float*)(smem + OFF_ST);            // [qr][16][64]
    float* lbuf = (float*)(smem + OFF_ST + 16384);    // [64]

    if (h == 1) {
        float* base = obuf + qr * 1024;
        #pragma unroll
        for (int j = 0; j < 8; ++j) {
            *(float2*)(base + g * 64 + 8 * j + 2 * t)       = make_float2(o[j][0], o[j][1]);
            *(float2*)(base + (g + 8) * 64 + 8 * j + 2 * t) = make_float2(o[j][2], o[j][3]);
        }
        if (t == 0) { lbuf[qr * 16 + g] = lsum0; lbuf[qr * 16 + g + 8] = lsum1; }
    }
    __syncthreads();
    if (h == 0) {
        float* base = obuf + qr * 1024;
        lsum0 += lbuf[qr * 16 + g];
        lsum1 += lbuf[qr * 16 + g + 8];
        const float inv0 = 1.0f / lsum0;
        const float inv1 = 1.0f / lsum1;
        float* o0 = out + (bNN + qrow) * DD + 2 * t;
        float* o1 = o0 + 8 * DD;
        #pragma unroll
        for (int j = 0; j < 8; ++j) {
            float2 p0 = *(float2*)(base + g * 64 + 8 * j + 2 * t);
            float2 p1 = *(float2*)(base + (g + 8) * 64 + 8 * j + 2 * t);
            *(float2*)(o0 + 8 * j) = make_float2((o[j][0] + p0.x) * inv0, (o[j][1] + p0.y) * inv0);
            *(float2*)(o1 + 8 * j) = make_float2((o[j][2] + p1.x) * inv1, (o[j][3] + p1.y) * inv1);
        }
    }
}

// ---------------------------------------------------------------------------
extern "C" void kernel_launch(void* const* d_in, const int* in_sizes, int n_in,
                              void* d_out, int out_size) {
    (void)in_sizes; (void)n_in; (void)out_size;
    const float* x    = (const float*)d_in[0];
    const float* adj  = (const float*)d_in[1];
    const float* beta = (const float*)d_in[2];
    float* out = (float*)d_out;

    prep_kernel<<<BB * NN / 64, 256>>>(x, beta);

    cudaFuncSetAttribute(attn_mma, cudaFuncAttributeMaxDynamicSharedMemorySize, SMEM_TOTAL);
    dim3 grid(NN / TM, BB);
    attn_mma<<<grid, 256, SMEM_TOTAL>>>(x, adj, beta, out);
}

// round 9
// speedup vs baseline: 1.2199x; 1.0477x over previous
#include <cuda_runtime.h>
#include <cuda_bf16.h>
#include <cstdint>

#define BB 4
#define NN 4096
#define DD 64
#define TM 64
#define TN 64
#define NTILES (NN / TN)
#define DOT_TOL 0.1f

// ---------------- device scratch (allocation-free) ----------------
__device__ __align__(16) __nv_bfloat16 g_xhi [BB * NN * DD];
__device__ __align__(16) __nv_bfloat16 g_xlo [BB * NN * DD];
__device__ __align__(16) __nv_bfloat16 g_xThi[BB * DD * NN];
__device__ __align__(16) __nv_bfloat16 g_xTlo[BB * DD * NN];
__device__ __align__(16) float g_rn [BB * NN];
__device__ __align__(16) float g_rnb[BB * NN];

// ---------------- helpers ----------------
__device__ __forceinline__ uint32_t smem_u32(const void* p) {
    uint32_t a;
    asm("{ .reg .u64 t; cvta.to.shared.u64 t, %1; cvt.u32.u64 %0, t; }" : "=r"(a) : "l"(p));
    return a;
}
#define SW(o) ((o) ^ (((o) >> 3) & 0x70))
#define CPA(dst, src) asm volatile("cp.async.cg.shared.global [%0], [%1], 16;" :: "r"(dst), "l"(src))
#define CPC()   asm volatile("cp.async.commit_group;" ::: "memory")
#define CPW0()  asm volatile("cp.async.wait_group 0;" ::: "memory")

__device__ __forceinline__ void ldsm4(uint32_t& r0, uint32_t& r1, uint32_t& r2, uint32_t& r3, uint32_t a) {
    asm volatile("ldmatrix.sync.aligned.m8n8.x4.shared.b16 {%0,%1,%2,%3}, [%4];"
                 : "=r"(r0), "=r"(r1), "=r"(r2), "=r"(r3) : "r"(a));
}
__device__ __forceinline__ void mma16816(float* d, const uint32_t* a, const uint32_t* b) {
    asm volatile("mma.sync.aligned.m16n8k16.row.col.f32.bf16.bf16.f32 "
                 "{%0,%1,%2,%3}, {%4,%5,%6,%7}, {%8,%9}, {%0,%1,%2,%3};"
                 : "+f"(d[0]), "+f"(d[1]), "+f"(d[2]), "+f"(d[3])
                 : "r"(a[0]), "r"(a[1]), "r"(a[2]), "r"(a[3]), "r"(b[0]), "r"(b[1]));
}
__device__ __forceinline__ uint32_t pack2(__nv_bfloat16 a, __nv_bfloat16 b) {
    return (uint32_t)__bfloat16_as_ushort(a) | ((uint32_t)__bfloat16_as_ushort(b) << 16);
}

// cold-path exact fp32 dot (sign rescue)
__device__ __noinline__ float dot64(const float* __restrict__ a, const float* __restrict__ b) {
    float acc = 0.f;
    #pragma unroll
    for (int i = 0; i < 16; ++i) {
        float4 va = __ldg((const float4*)a + i);
        float4 vb = __ldg((const float4*)b + i);
        acc = fmaf(va.x, vb.x, acc); acc = fmaf(va.y, vb.y, acc);
        acc = fmaf(va.z, vb.z, acc); acc = fmaf(va.w, vb.w, acc);
    }
    return acc;
}

// ---------------- prep ----------------
__global__ __launch_bounds__(256) void prep_kernel(const float* __restrict__ x,
                                                   const float* __restrict__ betap) {
    __shared__ float s[64][68];
    const int row0 = blockIdx.x * 64;
    const int tid = threadIdx.x;

    for (int i = tid; i < 64 * 16; i += 256) {
        int r = i >> 4, c4 = (i & 15) << 2;
        float4 v = *(const float4*)&x[(size_t)(row0 + r) * DD + c4];
        s[r][c4] = v.x; s[r][c4 + 1] = v.y; s[r][c4 + 2] = v.z; s[r][c4 + 3] = v.w;
    }
    __syncthreads();

    const float beta = __ldg(betap);
    if (tid < 64) {
        float acc = 0.f;
        #pragma unroll
        for (int d = 0; d < 64; ++d) acc = fmaf(s[tid][d], s[tid][d], acc);
        float rn = 1.0f / sqrtf(acc);
        g_rn[row0 + tid] = rn;
        g_rnb[row0 + tid] = beta * rn;
    }

    {   // row-major hi/lo
        int base = tid * 16;
        int r = base >> 6, c = base & 63;
        uint32_t hb[8], lb[8];
        #pragma unroll
        for (int j = 0; j < 8; ++j) {
            float a = s[r][c + 2 * j], b = s[r][c + 2 * j + 1];
            __nv_bfloat16 ah = __float2bfloat16(a), bh = __float2bfloat16(b);
            __nv_bfloat16 al = __float2bfloat16(a - __bfloat162float(ah));
            __nv_bfloat16 bl = __float2bfloat16(b - __bfloat162float(bh));
            hb[j] = pack2(ah, bh); lb[j] = pack2(al, bl);
        }
        uint4* dh = (uint4*)(g_xhi + (size_t)row0 * DD + base);
        uint4* dl = (uint4*)(g_xlo + (size_t)row0 * DD + base);
        dh[0] = make_uint4(hb[0], hb[1], hb[2], hb[3]); dh[1] = make_uint4(hb[4], hb[5], hb[6], hb[7]);
        dl[0] = make_uint4(lb[0], lb[1], lb[2], lb[3]); dl[1] = make_uint4(lb[4], lb[5], lb[6], lb[7]);
    }
    {   // transposed hi/lo
        int d = tid >> 2, j0 = (tid & 3) * 16;
        int b = row0 / NN, n0 = row0 % NN;
        uint32_t hb[8], lb[8];
        #pragma unroll
        for (int j = 0; j < 8; ++j) {
            float a = s[j0 + 2 * j][d], bb = s[j0 + 2 * j + 1][d];
            __nv_bfloat16 ah = __float2bfloat16(a), bh = __float2bfloat16(bb);
            __nv_bfloat16 al = __float2bfloat16(a - __bfloat162float(ah));
            __nv_bfloat16 bl = __float2bfloat16(bb - __bfloat162float(bh));
            hb[j] = pack2(ah, bh); lb[j] = pack2(al, bl);
        }
        size_t off = (size_t)(b * DD + d) * NN + n0 + j0;
        uint4* dh = (uint4*)(g_xThi + off);
        uint4* dl = (uint4*)(g_xTlo + off);
        dh[0] = make_uint4(hb[0], hb[1], hb[2], hb[3]); dh[1] = make_uint4(hb[4], hb[5], hb[6], hb[7]);
        dl[0] = make_uint4(lb[0], lb[1], lb[2], lb[3]); dl[1] = make_uint4(lb[4], lb[5], lb[6], lb[7]);
    }
}

// ---------------- smem layout ----------------
// Q hi: 8K; 2 stages x (Khi 8K | Klo 8K | Vhi 8K | Vlo 8K | adj 64x272B)
#define OFF_Q       0
#define OFF_ST      8192
#define OFF_ADJ     32768                   // within a stage
#define ADJ_PITCH   272                     // 64 floats + 16B pad (bank spread)
#define STAGE_BYTES (32768 + 64 * ADJ_PITCH)  // 50176
#define SMEM_TOTAL  (8192 + 2 * STAGE_BYTES)  // 108544

__device__ __forceinline__ void load_stage(uint32_t stbase, int tid, int b, int q0, int k0,
                                           const float* __restrict__ adj) {
    const __nv_bfloat16* kh = g_xhi + ((size_t)b * NN + k0) * DD;
    const __nv_bfloat16* kl = g_xlo + ((size_t)b * NN + k0) * DD;
    const __nv_bfloat16* vh = g_xThi + (size_t)b * DD * NN + k0;
    const __nv_bfloat16* vl = g_xTlo + (size_t)b * DD * NN + k0;
    #pragma unroll
    for (int it = 0; it < 8; ++it) {
        int m = tid + it * 256;
        int buf = m >> 9, idx = m & 511, r = idx >> 3, c = idx & 7;
        uint32_t dst = stbase + buf * 8192 + SW(r * 128 + c * 16);
        const __nv_bfloat16* src;
        if (buf == 0)      src = kh + r * 64 + c * 8;
        else if (buf == 1) src = kl + r * 64 + c * 8;
        else if (buf == 2) src = vh + (size_t)r * NN + c * 8;
        else               src = vl + (size_t)r * NN + c * 8;
        CPA(dst, src);
    }
    // adj tile: 64 rows x 64 fp32, 16B chunks, padded pitch
    const float* ab = adj + ((size_t)b * NN + q0) * NN + k0;
    #pragma unroll
    for (int it = 0; it < 4; ++it) {
        int m = tid + it * 256;          // 0..1023
        int r = m >> 4, c = m & 15;
        CPA(stbase + OFF_ADJ + r * ADJ_PITCH + c * 16, ab + (size_t)r * NN + c * 4);
    }
}

// ---------------- main kernel: 256 threads, key-split warps, 2 CTAs/SM ----------------
__global__ __launch_bounds__(256, 2)
void attn_mma(const float* __restrict__ x,
              const float* __restrict__ adj,
              const float* __restrict__ betap,
              float* __restrict__ out) {
    extern __shared__ char smem[];
    const uint32_t sb = smem_u32(smem);
    const int tid = threadIdx.x;
    const int wid = tid >> 5, lane = tid & 31;
    const int qr = wid >> 1;          // query row group: rows 16*qr .. 16*qr+15
    const int h  = wid & 1;           // key half within tile: keys 32h .. 32h+31
    const int g = lane >> 2, t = lane & 3;
    const int b = blockIdx.y, q0 = blockIdx.x * TM;
    const size_t bNN = (size_t)b * NN;

    const int lm = lane >> 3, li = lane & 7;
    const uint32_t b_row = ((lm >> 1) << 3) + li;
    const uint32_t b_kb  = (uint32_t)(lm & 1) << 4;
    const uint32_t a_row = ((uint32_t)(lm & 1) << 3) + li + qr * 16;
    const uint32_t a_kb  = (uint32_t)(lm >> 1) << 4;

    // prologue: Q hi + tile0 (K/V/adj)
    {
        const __nv_bfloat16* qh = g_xhi + (bNN + q0) * DD;
        #pragma unroll
        for (int it = 0; it < 2; ++it) {
            int m = tid + it * 256;
            int r = m >> 3, c = m & 7;
            CPA(sb + OFF_Q + SW(r * 128 + c * 16), qh + r * 64 + c * 8);
        }
        load_stage(sb + OFF_ST, tid, b, q0, 0, adj);
        CPC();
    }

    const float beta = __ldg(betap);
    const float C = beta + 10.0f;
    const int qrow = q0 + qr * 16 + g;
    const float rq0 = g_rn[bNN + qrow];
    const float rq1 = g_rn[bNN + qrow + 8];
    const float* xb  = x + bNN * DD;
    const float* xq0 = xb + (size_t)qrow * DD;
    const float* xq1 = xq0 + 8 * DD;
    // per-thread adj smem byte offset within a stage
    const int adj_off = OFF_ADJ + (qr * 16 + g) * ADJ_PITCH + (32 * h + 2 * t) * 4;

    uint32_t qhiF[4][4];
    float o[8][4];
    #pragma unroll
    for (int j = 0; j < 8; ++j)
        { o[j][0] = 0.f; o[j][1] = 0.f; o[j][2] = 0.f; o[j][3] = 0.f; }
    float lsum0 = 0.f, lsum1 = 0.f;

    for (int tt = 0; tt < NTILES; ++tt) {
        const int k0 = tt * TN;
        CPW0();
        __syncthreads();
        if (tt + 1 < NTILES) {
            load_stage(sb + OFF_ST + ((tt + 1) & 1) * STAGE_BYTES, tid, b, q0, k0 + TN, adj);
            CPC();
        }
        if (tt == 0) {
            #pragma unroll
            for (int ks = 0; ks < 4; ++ks) {
                uint32_t ad = sb + OFF_Q + SW(a_row * 128 + ks * 32 + a_kb);
                ldsm4(qhiF[ks][0], qhiF[ks][1], qhiF[ks][2], qhiF[ks][3], ad);
            }
        }
        const int stoff = OFF_ST + (tt & 1) * STAGE_BYTES;
        const uint32_t stb = sb + stoff;
        const float* sa0 = (const float*)(smem + stoff + adj_off - OFF_ADJ + OFF_ADJ); // row g
        const float* sa1 = (const float*)((const char*)sa0 + 8 * ADJ_PITCH);           // row g+8

        // ---- S = Qhi*(Khi + Klo), 16x32 tile per warp ----
        float s[4][4];
        #pragma unroll
        for (int j = 0; j < 4; ++j)
            { s[j][0] = 0.f; s[j][1] = 0.f; s[j][2] = 0.f; s[j][3] = 0.f; }

        #pragma unroll
        for (int ks = 0; ks < 4; ++ks) {
            uint32_t bf[4][2];
            #pragma unroll
            for (int nb = 0; nb < 2; ++nb) {
                uint32_t ad = stb + SW((32 * h + nb * 16 + b_row) * 128 + ks * 32 + b_kb);
                ldsm4(bf[2 * nb][0], bf[2 * nb][1], bf[2 * nb + 1][0], bf[2 * nb + 1][1], ad);
            }
            #pragma unroll
            for (int j = 0; j < 4; ++j) mma16816(s[j], qhiF[ks], bf[j]);
            #pragma unroll
            for (int nb = 0; nb < 2; ++nb) {
                uint32_t ad = stb + 8192 + SW((32 * h + nb * 16 + b_row) * 128 + ks * 32 + b_kb);
                ldsm4(bf[2 * nb][0], bf[2 * nb][1], bf[2 * nb + 1][0], bf[2 * nb + 1][1], ad);
            }
            #pragma unroll
            for (int j = 0; j < 4; ++j) mma16816(s[j], qhiF[ks], bf[j]);
        }

        // ---- logits -> exp -> pack P (adj from smem) ----
        uint32_t ahi[2][4], alo[2][4];
        {
            const float* rnbp = g_rnb + bNN + k0 + 32 * h + 2 * t;
            #pragma unroll
            for (int j = 0; j < 4; ++j) {
                float2 av0 = *(const float2*)(sa0 + 8 * j);
                float2 av1 = *(const float2*)(sa1 + 8 * j);
                {   // cold fp32 sign rescue
                    bool n0 = (av0.x > 0.5f) && (fabsf(s[j][0]) < DOT_TOL);
                    bool n1 = (av0.y > 0.5f) && (fabsf(s[j][1]) < DOT_TOL);
                    bool n2 = (av1.x > 0.5f) && (fabsf(s[j][2]) < DOT_TOL);
                    bool n3 = (av1.y > 0.5f) && (fabsf(s[j][3]) < DOT_TOL);
                    if (n0 | n1 | n2 | n3) {
                        const int kk = k0 + 32 * h + 8 * j + 2 * t;
                        if (n0) s[j][0] = dot64(xq0, xb + (size_t)kk * DD);
                        if (n1) s[j][1] = dot64(xq0, xb + (size_t)(kk + 1) * DD);
                        if (n2) s[j][2] = dot64(xq1, xb + (size_t)kk * DD);
                        if (n3) s[j][3] = dot64(xq1, xb + (size_t)(kk + 1) * DD);
                    }
                }
                float2 rk = __ldg((const float2*)(rnbp + 8 * j));
                float lg0 = (s[j][0] < 0.f) ? -1e30f : fmaf(10.f, av0.x, fmaf(s[j][0], rq0 * rk.x, -C));
                float lg1 = (s[j][1] < 0.f) ? -1e30f : fmaf(10.f, av0.y, fmaf(s[j][1], rq0 * rk.y, -C));
                float lg2 = (s[j][2] < 0.f) ? -1e30f : fmaf(10.f, av1.x, fmaf(s[j][2], rq1 * rk.x, -C));
                float lg3 = (s[j][3] < 0.f) ? -1e30f : fmaf(10.f, av1.y, fmaf(s[j][3], rq1 * rk.y, -C));
                float p0 = __expf(lg0), p1 = __expf(lg1), p2 = __expf(lg2), p3 = __expf(lg3);
                lsum0 += p0 + p1; lsum1 += p2 + p3;
                uint32_t h01, h23;
                asm("cvt.rn.bf16x2.f32 %0, %1, %2;" : "=r"(h01) : "f"(p1), "f"(p0));
                asm("cvt.rn.bf16x2.f32 %0, %1, %2;" : "=r"(h23) : "f"(p3), "f"(p2));
                float hf0 = __uint_as_float(h01 << 16), hf1 = __uint_as_float(h01 & 0xFFFF0000u);
                float hf2 = __uint_as_float(h23 << 16), hf3 = __uint_as_float(h23 & 0xFFFF0000u);
                uint32_t l01, l23;
                asm("cvt.rn.bf16x2.f32 %0, %1, %2;" : "=r"(l01) : "f"(p1 - hf1), "f"(p0 - hf0));
                asm("cvt.rn.bf16x2.f32 %0, %1, %2;" : "=r"(l23) : "f"(p3 - hf3), "f"(p2 - hf2));
                int cc = j >> 1, hp = (j & 1) << 1;
                ahi[cc][hp] = h01; ahi[cc][hp + 1] = h23;
                alo[cc][hp] = l01; alo[cc][hp + 1] = l23;
            }
        }

        // ---- O += P V over this warp's 32 keys, all 64 dims ----
        #pragma unroll
        for (int cl = 0; cl < 2; ++cl) {
            const int c = 2 * h + cl;
            uint32_t bf[8][2];
            #pragma unroll
            for (int nb = 0; nb < 4; ++nb) {
                uint32_t ad = stb + 16384 + SW((nb * 16 + b_row) * 128 + c * 32 + b_kb);
                ldsm4(bf[2 * nb][0], bf[2 * nb][1], bf[2 * nb + 1][0], bf[2 * nb + 1][1], ad);
            }
            #pragma unroll
            for (int j = 0; j < 8; ++j) { mma16816(o[j], ahi[cl], bf[j]); mma16816(o[j], alo[cl], bf[j]); }
            #pragma unroll
            for (int nb = 0; nb < 4; ++nb) {
                uint32_t ad = stb + 24576 + SW((nb * 16 + b_row) * 128 + c * 32 + b_kb);
                ldsm4(bf[2 * nb][0], bf[2 * nb][1], bf[2 * nb + 1][0], bf[2 * nb + 1][1], ad);
            }
            #pragma unroll
            for (int j = 0; j < 8; ++j) mma16816(o[j], ahi[cl], bf[j]);
        }
    }

    // ---- epilogue: combine key halves via smem, normalize, store ----
    lsum0 += __shfl_xor_sync(0xffffffffu, lsum0, 1);
    lsum0 += __shfl_xor_sync(0xffffffffu, lsum0, 2);
    lsum1 += __shfl_xor_sync(0xffffffffu, lsum1, 1);
    lsum1 += __shfl_xor_sync(0xffffffffu, lsum1, 2);

    __syncthreads();   // all stage-buffer reads done; safe to reuse as O buffer
    float* obuf = (float*)(smem + OFF_ST);            // [qr][16][64]
    float* lbuf = (float*)(smem + OFF_ST + 16384);    // [64]

    if (h == 1) {
        float* base = obuf + qr * 1024;
        #pragma unroll
        for (int j = 0; j < 8; ++j) {
            *(float2*)(base + g * 64 + 8 * j + 2 * t)       = make_float2(o[j][0], o[j][1]);
            *(float2*)(base + (g + 8) * 64 + 8 * j + 2 * t) = make_float2(o[j][2], o[j][3]);
        }
        if (t == 0) { lbuf[qr * 16 + g] = lsum0; lbuf[qr * 16 + g + 8] = lsum1; }
    }
    __syncthreads();
    if (h == 0) {
        float* base = obuf + qr * 1024;
        lsum0 += lbuf[qr * 16 + g];
        lsum1 += lbuf[qr * 16 + g + 8];
        const float inv0 = 1.0f / lsum0;
        const float inv1 = 1.0f / lsum1;
        float* o0 = out + (bNN + qrow) * DD + 2 * t;
        float* o1 = o0 + 8 * DD;
        #pragma unroll
        for (int j = 0; j < 8; ++j) {
            float2 p0 = *(float2*)(base + g * 64 + 8 * j + 2 * t);
            float2 p1 = *(float2*)(base + (g + 8) * 64 + 8 * j + 2 * t);
            *(float2*)(o0 + 8 * j) = make_float2((o[j][0] + p0.x) * inv0, (o[j][1] + p0.y) * inv0);
            *(float2*)(o1 + 8 * j) = make_float2((o[j][2] + p1.x) * inv1, (o[j][3] + p1.y) * inv1);
        }
    }
}

// ---------------------------------------------------------------------------
extern "C" void kernel_launch(void* const* d_in, const int* in_sizes, int n_in,
                              void* d_out, int out_size) {
    (void)in_sizes; (void)n_in; (void)out_size;
    const float* x    = (const float*)d_in[0];
    const float* adj  = (const float*)d_in[1];
    const float* beta = (const float*)d_in[2];
    float* out = (float*)d_out;

    prep_kernel<<<BB * NN / 64, 256>>>(x, beta);

    cudaFuncSetAttribute(attn_mma, cudaFuncAttributeMaxDynamicSharedMemorySize, SMEM_TOTAL);
    dim3 grid(NN / TM, BB);
    attn_mma<<<grid, 256, SMEM_TOTAL>>>(x, adj, beta, out);
}

// round 11
// speedup vs baseline: 1.3859x; 1.1360x over previous
#include <cuda_runtime.h>
#include <cuda_fp16.h>
#include <cstdint>

#define BB 4
#define NN 4096
#define DD 64
#define TM 64
#define TN 64
#define NTILES (NN / TN)
#define DOT_TOL 0.1f

// ---------------- device scratch (allocation-free) ----------------
__device__ __align__(16) __half g_xhi [BB * NN * DD];   // row-major fp16 hi (Q & K)
__device__ __align__(16) __half g_xThi[BB * DD * NN];   // transposed fp16 hi [b][d][n]
__device__ __align__(16) __half g_xTlo[BB * DD * NN];   // transposed fp16 lo
__device__ __align__(16) float g_rn [BB * NN];
__device__ __align__(16) float g_rnb[BB * NN];

// ---------------- helpers ----------------
__device__ __forceinline__ uint32_t smem_u32(const void* p) {
    uint32_t a;
    asm("{ .reg .u64 t; cvta.to.shared.u64 t, %1; cvt.u32.u64 %0, t; }" : "=r"(a) : "l"(p));
    return a;
}
#define SW(o) ((o) ^ (((o) >> 3) & 0x70))
#define CPA(dst, src) asm volatile("cp.async.cg.shared.global [%0], [%1], 16;" :: "r"(dst), "l"(src))
#define CPC()   asm volatile("cp.async.commit_group;" ::: "memory")
#define CPW0()  asm volatile("cp.async.wait_group 0;" ::: "memory")

__device__ __forceinline__ void ldsm4(uint32_t& r0, uint32_t& r1, uint32_t& r2, uint32_t& r3, uint32_t a) {
    asm volatile("ldmatrix.sync.aligned.m8n8.x4.shared.b16 {%0,%1,%2,%3}, [%4];"
                 : "=r"(r0), "=r"(r1), "=r"(r2), "=r"(r3) : "r"(a));
}
__device__ __forceinline__ void mma16816(float* d, const uint32_t* a, const uint32_t* b) {
    asm volatile("mma.sync.aligned.m16n8k16.row.col.f32.f16.f16.f32 "
                 "{%0,%1,%2,%3}, {%4,%5,%6,%7}, {%8,%9}, {%0,%1,%2,%3};"
                 : "+f"(d[0]), "+f"(d[1]), "+f"(d[2]), "+f"(d[3])
                 : "r"(a[0]), "r"(a[1]), "r"(a[2]), "r"(a[3]), "r"(b[0]), "r"(b[1]));
}
__device__ __forceinline__ uint32_t pack2h(__half a, __half b) {
    return (uint32_t)__half_as_ushort(a) | ((uint32_t)__half_as_ushort(b) << 16);
}

// cold-path exact fp32 dot (sign rescue)
__device__ __noinline__ float dot64(const float* __restrict__ a, const float* __restrict__ b) {
    float acc = 0.f;
    #pragma unroll
    for (int i = 0; i < 16; ++i) {
        float4 va = __ldg((const float4*)a + i);
        float4 vb = __ldg((const float4*)b + i);
        acc = fmaf(va.x, vb.x, acc); acc = fmaf(va.y, vb.y, acc);
        acc = fmaf(va.z, vb.z, acc); acc = fmaf(va.w, vb.w, acc);
    }
    return acc;
}

// ---------------- prep ----------------
__global__ __launch_bounds__(256) void prep_kernel(const float* __restrict__ x,
                                                   const float* __restrict__ betap) {
    __shared__ float s[64][68];
    const int row0 = blockIdx.x * 64;
    const int tid = threadIdx.x;

    for (int i = tid; i < 64 * 16; i += 256) {
        int r = i >> 4, c4 = (i & 15) << 2;
        float4 v = *(const float4*)&x[(size_t)(row0 + r) * DD + c4];
        s[r][c4] = v.x; s[r][c4 + 1] = v.y; s[r][c4 + 2] = v.z; s[r][c4 + 3] = v.w;
    }
    __syncthreads();

    const float beta = __ldg(betap);
    if (tid < 64) {
        float acc = 0.f;
        #pragma unroll
        for (int d = 0; d < 64; ++d) acc = fmaf(s[tid][d], s[tid][d], acc);
        float rn = 1.0f / sqrtf(acc);
        g_rn[row0 + tid] = rn;
        g_rnb[row0 + tid] = beta * rn;
    }

    {   // row-major fp16 hi (Q & K operand)
        int base = tid * 16;
        int r = base >> 6, c = base & 63;
        uint32_t hb[8];
        #pragma unroll
        for (int j = 0; j < 8; ++j) {
            __half ah = __float2half_rn(s[r][c + 2 * j]);
            __half bh = __float2half_rn(s[r][c + 2 * j + 1]);
            hb[j] = pack2h(ah, bh);
        }
        uint4* dh = (uint4*)(g_xhi + (size_t)row0 * DD + base);
        dh[0] = make_uint4(hb[0], hb[1], hb[2], hb[3]);
        dh[1] = make_uint4(hb[4], hb[5], hb[6], hb[7]);
    }
    {   // transposed fp16 hi/lo (V operand)
        int d = tid >> 2, j0 = (tid & 3) * 16;
        int b = row0 / NN, n0 = row0 % NN;
        uint32_t hb[8], lb[8];
        #pragma unroll
        for (int j = 0; j < 8; ++j) {
            float a = s[j0 + 2 * j][d], bb = s[j0 + 2 * j + 1][d];
            __half ah = __float2half_rn(a), bh = __float2half_rn(bb);
            __half al = __float2half_rn(a - __half2float(ah));
            __half bl = __float2half_rn(bb - __half2float(bh));
            hb[j] = pack2h(ah, bh); lb[j] = pack2h(al, bl);
        }
        size_t off = (size_t)(b * DD + d) * NN + n0 + j0;
        uint4* dh = (uint4*)(g_xThi + off);
        uint4* dl = (uint4*)(g_xTlo + off);
        dh[0] = make_uint4(hb[0], hb[1], hb[2], hb[3]); dh[1] = make_uint4(hb[4], hb[5], hb[6], hb[7]);
        dl[0] = make_uint4(lb[0], lb[1], lb[2], lb[3]); dl[1] = make_uint4(lb[4], lb[5], lb[6], lb[7]);
    }
}

// ---------------- smem layout ----------------
// Q hi: 8K; 2 stages x (Khi 8K | Vhi 8K | Vlo 8K | adj 64x272B)
#define OFF_Q       0
#define OFF_ST      8192
#define OFF_VHI     8192                    // within a stage
#define OFF_VLO     16384
#define OFF_ADJ     24576
#define ADJ_PITCH   272
#define STAGE_BYTES (24576 + 64 * ADJ_PITCH)  // 41984
#define SMEM_TOTAL  (8192 + 2 * STAGE_BYTES)  // 92160

__device__ __forceinline__ void load_stage(uint32_t stbase, int tid, int b, int q0, int k0,
                                           const float* __restrict__ adj) {
    const __half* kh = g_xhi + ((size_t)b * NN + k0) * DD;
    const __half* vh = g_xThi + (size_t)b * DD * NN + k0;
    const __half* vl = g_xTlo + (size_t)b * DD * NN + k0;
    #pragma unroll
    for (int it = 0; it < 6; ++it) {
        int m = tid + it * 256;
        int buf = m >> 9, idx = m & 511, r = idx >> 3, c = idx & 7;
        uint32_t dst = stbase + buf * 8192 + SW(r * 128 + c * 16);
        const __half* src;
        if (buf == 0)      src = kh + r * 64 + c * 8;
        else if (buf == 1) src = vh + (size_t)r * NN + c * 8;
        else               src = vl + (size_t)r * NN + c * 8;
        CPA(dst, src);
    }
    // adj tile: 64 rows x 64 fp32
    const float* ab = adj + ((size_t)b * NN + q0) * NN + k0;
    #pragma unroll
    for (int it = 0; it < 4; ++it) {
        int m = tid + it * 256;          // 0..1023
        int r = m >> 4, c = m & 15;
        CPA(stbase + OFF_ADJ + r * ADJ_PITCH + c * 16, ab + (size_t)r * NN + c * 4);
    }
}

// ---------------- main kernel: 256 threads, key-split warps, 2 CTAs/SM ----------------
__global__ __launch_bounds__(256, 2)
void attn_mma(const float* __restrict__ x,
              const float* __restrict__ adj,
              const float* __restrict__ betap,
              float* __restrict__ out) {
    extern __shared__ char smem[];
    const uint32_t sb = smem_u32(smem);
    const int tid = threadIdx.x;
    const int wid = tid >> 5, lane = tid & 31;
    const int qr = wid >> 1;          // query rows 16*qr..16*qr+15
    const int h  = wid & 1;           // key half: keys 32h..32h+31
    const int g = lane >> 2, t = lane & 3;
    const int b = blockIdx.y, q0 = blockIdx.x * TM;
    const size_t bNN = (size_t)b * NN;

    const int lm = lane >> 3, li = lane & 7;
    const uint32_t b_row = ((lm >> 1) << 3) + li;
    const uint32_t b_kb  = (uint32_t)(lm & 1) << 4;
    const uint32_t a_row = ((uint32_t)(lm & 1) << 3) + li + qr * 16;
    const uint32_t a_kb  = (uint32_t)(lm >> 1) << 4;

    // prologue: Q hi + tile0
    {
        const __half* qh = g_xhi + (bNN + q0) * DD;
        #pragma unroll
        for (int it = 0; it < 2; ++it) {
            int m = tid + it * 256;
            int r = m >> 3, c = m & 7;
            CPA(sb + OFF_Q + SW(r * 128 + c * 16), qh + r * 64 + c * 8);
        }
        load_stage(sb + OFF_ST, tid, b, q0, 0, adj);
        CPC();
    }

    const float beta = __ldg(betap);
    const float C = beta + 10.0f;
    const int qrow = q0 + qr * 16 + g;
    const float rq0 = g_rn[bNN + qrow];
    const float rq1 = g_rn[bNN + qrow + 8];
    const float* xb  = x + bNN * DD;
    const float* xq0 = xb + (size_t)qrow * DD;
    const float* xq1 = xq0 + 8 * DD;
    const int adj_off = OFF_ADJ + (qr * 16 + g) * ADJ_PITCH + (32 * h + 2 * t) * 4;

    uint32_t qhiF[4][4];
    float o[8][4];
    #pragma unroll
    for (int j = 0; j < 8; ++j)
        { o[j][0] = 0.f; o[j][1] = 0.f; o[j][2] = 0.f; o[j][3] = 0.f; }
    float lsum0 = 0.f, lsum1 = 0.f;

    for (int tt = 0; tt < NTILES; ++tt) {
        const int k0 = tt * TN;
        CPW0();
        __syncthreads();
        if (tt + 1 < NTILES) {
            load_stage(sb + OFF_ST + ((tt + 1) & 1) * STAGE_BYTES, tid, b, q0, k0 + TN, adj);
            CPC();
        }
        if (tt == 0) {
            #pragma unroll
            for (int ks = 0; ks < 4; ++ks) {
                uint32_t ad = sb + OFF_Q + SW(a_row * 128 + ks * 32 + a_kb);
                ldsm4(qhiF[ks][0], qhiF[ks][1], qhiF[ks][2], qhiF[ks][3], ad);
            }
        }
        const int stoff = OFF_ST + (tt & 1) * STAGE_BYTES;
        const uint32_t stb = sb + stoff;
        const float* sa0 = (const float*)(smem + stoff + adj_off);        // row g
        const float* sa1 = (const float*)((const char*)sa0 + 8 * ADJ_PITCH);

        // ---- S = Qhi * Khi (single-term fp16, fp32 accum) ----
        float s[4][4];
        #pragma unroll
        for (int j = 0; j < 4; ++j)
            { s[j][0] = 0.f; s[j][1] = 0.f; s[j][2] = 0.f; s[j][3] = 0.f; }

        #pragma unroll
        for (int ks = 0; ks < 4; ++ks) {
            uint32_t bf[4][2];
            #pragma unroll
            for (int nb = 0; nb < 2; ++nb) {
                uint32_t ad = stb + SW((32 * h + nb * 16 + b_row) * 128 + ks * 32 + b_kb);
                ldsm4(bf[2 * nb][0], bf[2 * nb][1], bf[2 * nb + 1][0], bf[2 * nb + 1][1], ad);
            }
            #pragma unroll
            for (int j = 0; j < 4; ++j) mma16816(s[j], qhiF[ks], bf[j]);
        }

        // ---- logits -> exp -> pack P (fp16 hi only) ----
        uint32_t ahi[2][4];
        {
            const float* rnbp = g_rnb + bNN + k0 + 32 * h + 2 * t;
            #pragma unroll
            for (int j = 0; j < 4; ++j) {
                float2 av0 = *(const float2*)(sa0 + 8 * j);
                float2 av1 = *(const float2*)(sa1 + 8 * j);
                {   // cold fp32 sign rescue
                    bool n0 = (av0.x > 0.5f) && (fabsf(s[j][0]) < DOT_TOL);
                    bool n1 = (av0.y > 0.5f) && (fabsf(s[j][1]) < DOT_TOL);
                    bool n2 = (av1.x > 0.5f) && (fabsf(s[j][2]) < DOT_TOL);
                    bool n3 = (av1.y > 0.5f) && (fabsf(s[j][3]) < DOT_TOL);
                    if (n0 | n1 | n2 | n3) {
                        const int kk = k0 + 32 * h + 8 * j + 2 * t;
                        if (n0) s[j][0] = dot64(xq0, xb + (size_t)kk * DD);
                        if (n1) s[j][1] = dot64(xq0, xb + (size_t)(kk + 1) * DD);
                        if (n2) s[j][2] = dot64(xq1, xb + (size_t)kk * DD);
                        if (n3) s[j][3] = dot64(xq1, xb + (size_t)(kk + 1) * DD);
                    }
                }
                float2 rk = __ldg((const float2*)(rnbp + 8 * j));
                float lg0 = (s[j][0] < 0.f) ? -1e30f : fmaf(10.f, av0.x, fmaf(s[j][0], rq0 * rk.x, -C));
                float lg1 = (s[j][1] < 0.f) ? -1e30f : fmaf(10.f, av0.y, fmaf(s[j][1], rq0 * rk.y, -C));
                float lg2 = (s[j][2] < 0.f) ? -1e30f : fmaf(10.f, av1.x, fmaf(s[j][2], rq1 * rk.x, -C));
                float lg3 = (s[j][3] < 0.f) ? -1e30f : fmaf(10.f, av1.y, fmaf(s[j][3], rq1 * rk.y, -C));
                float p0 = __expf(lg0), p1 = __expf(lg1), p2 = __expf(lg2), p3 = __expf(lg3);
                lsum0 += p0 + p1; lsum1 += p2 + p3;
                uint32_t h01, h23;
                asm("cvt.rn.f16x2.f32 %0, %1, %2;" : "=r"(h01) : "f"(p1), "f"(p0));
                asm("cvt.rn.f16x2.f32 %0, %1, %2;" : "=r"(h23) : "f"(p3), "f"(p2));
                int cc = j >> 1, hp = (j & 1) << 1;
                ahi[cc][hp] = h01; ahi[cc][hp + 1] = h23;
            }
        }

        // ---- O += Phi * (Vhi + Vlo) over this warp's 32 keys, all 64 dims ----
        #pragma unroll
        for (int cl = 0; cl < 2; ++cl) {
            const int c = 2 * h + cl;
            uint32_t bf[8][2];
            #pragma unroll
            for (int nb = 0; nb < 4; ++nb) {
                uint32_t ad = stb + OFF_VHI + SW((nb * 16 + b_row) * 128 + c * 32 + b_kb);
                ldsm4(bf[2 * nb][0], bf[2 * nb][1], bf[2 * nb + 1][0], bf[2 * nb + 1][1], ad);
            }
            #pragma unroll
            for (int j = 0; j < 8; ++j) mma16816(o[j], ahi[cl], bf[j]);
            #pragma unroll
            for (int nb = 0; nb < 4; ++nb) {
                uint32_t ad = stb + OFF_VLO + SW((nb * 16 + b_row) * 128 + c * 32 + b_kb);
                ldsm4(bf[2 * nb][0], bf[2 * nb][1], bf[2 * nb + 1][0], bf[2 * nb + 1][1], ad);
            }
            #pragma unroll
            for (int j = 0; j < 8; ++j) mma16816(o[j], ahi[cl], bf[j]);
        }
    }

    // ---- epilogue: combine key halves via smem, normalize, store ----
    lsum0 += __shfl_xor_sync(0xffffffffu, lsum0, 1);
    lsum0 += __shfl_xor_sync(0xffffffffu, lsum0, 2);
    lsum1 += __shfl_xor_sync(0xffffffffu, lsum1, 1);
    lsum1 += __shfl_xor_sync(0xffffffffu, lsum1, 2);

    __syncthreads();
    float* obuf = (float*)(smem + OFF_ST);            // [qr][16][64]
    float* lbuf = (float*)(smem + OFF_ST + 16384);    // [64]

    if (h == 1) {
        float* base = obuf + qr * 1024;
        #pragma unroll
        for (int j = 0; j < 8; ++j) {
            *(float2*)(base + g * 64 + 8 * j + 2 * t)       = make_float2(o[j][0], o[j][1]);
            *(float2*)(base + (g + 8) * 64 + 8 * j + 2 * t) = make_float2(o[j][2], o[j][3]);
        }
        if (t == 0) { lbuf[qr * 16 + g] = lsum0; lbuf[qr * 16 + g + 8] = lsum1; }
    }
    __syncthreads();
    if (h == 0) {
        float* base = obuf + qr * 1024;
        lsum0 += lbuf[qr * 16 + g];
        lsum1 += lbuf[qr * 16 + g + 8];
        const float inv0 = 1.0f / lsum0;
        const float inv1 = 1.0f / lsum1;
        float* o0 = out + (bNN + qrow) * DD + 2 * t;
        float* o1 = o0 + 8 * DD;
        #pragma unroll
        for (int j = 0; j < 8; ++j) {
            float2 p0 = *(float2*)(base + g * 64 + 8 * j + 2 * t);
            float2 p1 = *(float2*)(base + (g + 8) * 64 + 8 * j + 2 * t);
            *(float2*)(o0 + 8 * j) = make_float2((o[j][0] + p0.x) * inv0, (o[j][1] + p0.y) * inv0);
            *(float2*)(o1 + 8 * j) = make_float2((o[j][2] + p1.x) * inv1, (o[j][3] + p1.y) * inv1);
        }
    }
}

// ---------------------------------------------------------------------------
extern "C" void kernel_launch(void* const* d_in, const int* in_sizes, int n_in,
                              void* d_out, int out_size) {
    (void)in_sizes; (void)n_in; (void)out_size;
    const float* x    = (const float*)d_in[0];
    const float* adj  = (const float*)d_in[1];
    const float* beta = (const float*)d_in[2];
    float* out = (float*)d_out;

    prep_kernel<<<BB * NN / 64, 256>>>(x, beta);

    cudaFuncSetAttribute(attn_mma, cudaFuncAttributeMaxDynamicSharedMemorySize, SMEM_TOTAL);
    dim3 grid(NN / TM, BB);
    attn_mma<<<grid, 256, SMEM_TOTAL>>>(x, adj, beta, out);
}